// round 11
// baseline (speedup 1.0000x reference)
#include <cuda_runtime.h>

// x: (1,8,12,12,12,8,40) f32 ; weight: (8,8,3,3,3,7) ; bias: (8,3,3,3)
// basis: (12,7,3,3) ; I,J: (8,40) i32 ; T: (12,8,40) i32 ; bias_basis: (96) i32
// out: (1,96,12,12,12,8,40) f32
//
// Fused per-voxel kernel (grid = 1728):
//  boundary voxel  -> zero its 96x320 slice
//  interior voxel  -> part1: Y[ob,h,w] = sum_{c,f} weight[o,c,f,b]*x[c,vox+f,h,w]  (smem, padded)
//                     part2: acc[g,o,p,q] = sum_{b,u,v} basis[g,b,u,v]*Y[o*7+b,p+u,q+v]
//                     gather: out[g*8+o,vox,h,w] = acc[T[g,h,w]*8+o, I-1, J-1] + biasSum

#define F_WSM   13824          // 216*64 : Wsm[(c*27+f)*64 + og*16 + j], j<14, out=og*14+j
#define YROW    44             // padded row (40 used)
#define YOBS    356            // per-(o,b) stride ; 356/4=89 == 1 mod 8 -> conflict-free
#define F_YS    (56*YOBS)      // 19936
#define F_ACCS  21888          // 96*6*38
#define F_BS    756

#define FMA2(acc, a, b) asm("fma.rn.f32x2 %0, %1, %2, %0;" : "+l"(acc) : "l"(a), "l"(b))
#define PACK2(dst, f)   asm("mov.b64 %0, {%1, %1};" : "=l"(dst) : "r"(__float_as_uint(f)))
#define PACKAB(dst, fa, fb) \
    asm("mov.b64 %0, {%1, %2};" : "=l"(dst) : "r"(__float_as_uint(fa)), "r"(__float_as_uint(fb)))
#define UNPACK2(lo, hi, v) asm("mov.b64 {%0, %1}, %2;" : "=r"(lo), "=r"(hi) : "l"(v))

__global__ __launch_bounds__(576, 1)
void fused(const float* __restrict__ x, const float* __restrict__ w,
           const float* __restrict__ basis, const float* __restrict__ bias,
           const int* __restrict__ Tg, const int* __restrict__ Ig,
           const int* __restrict__ Jg, const int* __restrict__ bbg,
           float* __restrict__ out)
{
    const int vox = blockIdx.x;
    const int vx = vox / 144, vy = (vox / 12) % 12, vz = vox % 12;
    const int tid = threadIdx.x;

    // ---- boundary voxel: zero the 96 x 320 slice ----
    if (vx < 1 || vx > 9 || vy < 1 || vy > 9 || vz < 1 || vz > 9) {
        const float4 z4 = make_float4(0.f, 0.f, 0.f, 0.f);
        float* ob = out + (size_t)vox * 320;
        for (int i = tid; i < 7680; i += 576) {
            const int ch = i / 80, off = (i % 80) * 4;
            *reinterpret_cast<float4*>(ob + (size_t)ch * 552960 + off) = z4;
        }
        return;
    }

    extern __shared__ __align__(16) float sm[];
    float* Wsm    = sm;                 // 13824
    float* Ys     = sm + F_WSM;         // Ys[ob*356 + h*44 + w]
    float* accS   = Ys + F_YS;          // accS[((g*8+o)*6+p)*38 + q]
    float* Bs     = accS + F_ACCS;      // basis copy
    float* bias_s = Bs + F_BS;          // 8 sums
    int*   bb_s   = (int*)(bias_s + 8); // 96

    // ---- cooperative preamble ----
    for (int idx = tid; idx < 12096; idx += 576) {
        int o = idx / 1512;  int r = idx - o * 1512;   // weight idx = o*1512 + c*189 + f*7 + b
        int c = r / 189;     r -= c * 189;
        int f = r / 7;       int b = r - f * 7;
        const int outc = o * 7 + b;                    // 0..55
        const int og = outc / 14, j = outc - og * 14;
        Wsm[(c * 27 + f) * 64 + og * 16 + j] = w[idx];
    }
    for (int i = tid; i < F_BS; i += 576) Bs[i] = basis[i];
    if (tid < 96) bb_s[tid] = bbg[tid];
    if (tid < 8) {
        float s = 0.f;
        for (int k = 0; k < 27; k++) s += bias[tid * 27 + k];
        bias_s[tid] = s;
    }
    __syncthreads();

    const int xo = vx - 1, yo = vy - 1, zo = vz - 1;

    // ---- part 1: Y = weight (*) x  (320 threads: 4 og-groups x 80 hw-quads,
    //      each thread 14 outputs x 4 w, FFMA2 throughout) ----
    if (tid < 320) {
        const int og  = tid / 80;            // 0..3 -> outputs [og*14, og*14+14)
        const int hwb = (tid % 80) * 4;
        // x strides (floats): c:552960  xi:46080  yi:3840  zi:320
        const float* xb = x + xo * 46080 + yo * 3840 + zo * 320 + hwb;

        unsigned long long a64[7][4];        // [out pair jp][x elem k]
#pragma unroll
        for (int jp = 0; jp < 7; jp++)
#pragma unroll
            for (int k = 0; k < 4; k++) a64[jp][k] = 0ull;

        for (int c = 0; c < 8; c++) {
            const float* xc = xb + c * 552960;
            for (int fi = 0; fi < 3; fi++) {
                const float* xcf = xc + fi * 46080;
                const float* wcf = Wsm + (c * 27 + fi * 9) * 64 + og * 16;
#pragma unroll
                for (int f9 = 0; f9 < 9; f9++) {
                    const int fj = f9 / 3, fk = f9 % 3;
                    const float4 xv = *reinterpret_cast<const float4*>(
                        xcf + fj * 3840 + fk * 320);
                    unsigned long long xq[4];
                    PACK2(xq[0], xv.x); PACK2(xq[1], xv.y);
                    PACK2(xq[2], xv.z); PACK2(xq[3], xv.w);
                    const float* wb = wcf + f9 * 64;   // 64B-aligned
                    const ulonglong2 wA = *reinterpret_cast<const ulonglong2*>(wb);      // pairs 0,1
                    const ulonglong2 wB = *reinterpret_cast<const ulonglong2*>(wb + 4);  // pairs 2,3
                    const ulonglong2 wC = *reinterpret_cast<const ulonglong2*>(wb + 8);  // pairs 4,5
                    const unsigned long long wD =
                        *reinterpret_cast<const unsigned long long*>(wb + 12);           // pair 6
#pragma unroll
                    for (int k = 0; k < 4; k++) {
                        FMA2(a64[0][k], wA.x, xq[k]);
                        FMA2(a64[1][k], wA.y, xq[k]);
                        FMA2(a64[2][k], wB.x, xq[k]);
                        FMA2(a64[3][k], wB.y, xq[k]);
                        FMA2(a64[4][k], wC.x, xq[k]);
                        FMA2(a64[5][k], wC.y, xq[k]);
                        FMA2(a64[6][k], wD,   xq[k]);
                    }
                }
            }
        }

        const int h = hwb / 40, w0 = hwb % 40;
#pragma unroll
        for (int jp = 0; jp < 7; jp++) {
            float r0[4], r1[4];
#pragma unroll
            for (int k = 0; k < 4; k++) {
                unsigned lo, hi;
                UNPACK2(lo, hi, a64[jp][k]);
                r0[k] = __uint_as_float(lo);
                r1[k] = __uint_as_float(hi);
            }
            float* p0 = Ys + (og * 14 + 2 * jp) * YOBS + h * YROW + w0;
            *reinterpret_cast<float4*>(p0)        = make_float4(r0[0], r0[1], r0[2], r0[3]);
            *reinterpret_cast<float4*>(p0 + YOBS) = make_float4(r1[0], r1[1], r1[2], r1[3]);
        }
    }
    __syncthreads();

    // ---- part 2: basis conv, thread = (g,o,p), tid == (g*8+o)*6+p, FFMA2 ----
    {
        const int g = tid / 48;
        const int o = (tid / 6) % 8;
        const int p = tid % 6;

        unsigned long long A[19];            // acc pairs (q=2k, 2k+1), q<38
#pragma unroll
        for (int k = 0; k < 19; k++) A[k] = 0ull;

        for (int b = 0; b < 7; b++) {
#pragma unroll
            for (int u = 0; u < 3; u++) {
                const float* yrow = Ys + (o * 7 + b) * YOBS + (p + u) * YROW;
                float r[40];
#pragma unroll
                for (int i = 0; i < 10; i++) {
                    const float4 v = reinterpret_cast<const float4*>(yrow)[i];
                    r[4*i] = v.x; r[4*i+1] = v.y; r[4*i+2] = v.z; r[4*i+3] = v.w;
                }
                const float* bp = Bs + ((g * 7 + b) * 3 + u) * 3;
                unsigned long long s0, s1, s2;
                PACK2(s0, bp[0]); PACK2(s1, bp[1]); PACK2(s2, bp[2]);

                unsigned long long P[20];
#pragma unroll
                for (int k = 0; k < 20; k++) PACKAB(P[k], r[2*k], r[2*k+1]);
#pragma unroll
                for (int k = 0; k < 19; k++) {
                    unsigned long long S;
                    PACKAB(S, r[2*k+1], r[2*k+2]);   // odd-aligned stream
                    FMA2(A[k], s0, P[k]);
                    FMA2(A[k], s1, S);
                    FMA2(A[k], s2, P[k+1]);
                }
            }
        }
        unsigned long long* ad =
            reinterpret_cast<unsigned long long*>(accS + tid * 38);  // 8B-aligned (152B stride)
#pragma unroll
        for (int k = 0; k < 19; k++) ad[k] = A[k];
    }
    __syncthreads();

    // ---- gather + write interior slice ----
    float* ob = out + (size_t)vox * 320;
    for (int idx = tid; idx < 30720; idx += 576) {
        const int go = idx / 320;
        const int hw = idx - go * 320;
        const int g  = go >> 3, o = go & 7;
        const int t  = Tg[g * 320 + hw];
        const int p  = Ig[hw] - 1;     // [0,5]
        const int q  = Jg[hw] - 1;     // [0,37]
        const float v = accS[((t * 8 + o) * 6 + p) * 38 + q] + bias_s[bb_s[t * 8 + o]];
        ob[(size_t)go * 552960 + hw] = v;
    }
}

// ---------------------------------------------------------------------------
extern "C" void kernel_launch(void* const* d_in, const int* in_sizes, int n_in,
                              void* d_out, int out_size)
{
    const float* x      = (const float*)d_in[0];
    const float* weight = (const float*)d_in[1];
    const float* bias   = (const float*)d_in[2];
    const float* basis  = (const float*)d_in[3];
    const int*   Ig     = (const int*)d_in[4];
    const int*   Jg     = (const int*)d_in[5];
    const int*   Tg     = (const int*)d_in[6];
    const int*   bbg    = (const int*)d_in[7];
    float*       out    = (float*)d_out;

    const size_t smem = (size_t)(F_WSM + F_YS + F_ACCS + F_BS + 8) * sizeof(float)
                      + 96 * sizeof(int);                       // 226,032 B
    cudaFuncSetAttribute(fused, cudaFuncAttributeMaxDynamicSharedMemorySize, (int)smem);
    fused<<<1728, 576, smem>>>(x, weight, basis, bias, Tg, Ig, Jg, bbg, out);
}

// round 12
// speedup vs baseline: 1.2708x; 1.2708x over previous
#include <cuda_runtime.h>

// x: (1,8,12,12,12,8,40) f32 ; weight: (8,8,3,3,3,7) ; bias: (8,3,3,3)
// basis: (12,7,3,3) ; I,J: (8,40) i32 ; T: (12,8,40) i32 ; bias_basis: (96) i32
// out: (1,96,12,12,12,8,40) f32
//
// Fused per-voxel kernel (grid = 1728):
//  boundary voxel  -> zero its 96x320 slice
//  interior voxel  -> part1: Y[ob,h,w] = sum_{c,f} weight[o,c,f,b]*x[c,vox+f,h,w]  (smem, padded)
//                     part2: acc[g,o,p,q] = sum_{b,u,v} basis[g,b,u,v]*Y[o*7+b,p+u,q+v]
//                     gather: out[g*8+o,vox,h,w] = acc[T[g,h,w]*8+o, I-1, J-1] + biasSum

#define F_WSM   12096          // 216*56 : Wsm[(c*27+f)*56 + o*7 + b]
#define YROW    44             // padded row (40 used)
#define YOBS    356            // per-(o,b) stride ; 356/4=89 == 1 mod 8 -> conflict-free
#define F_YS    (56*YOBS)      // 19936
#define F_ACCS  21888          // 96*6*38
#define F_BS    756

#define FMA2(acc, a, b) asm("fma.rn.f32x2 %0, %1, %2, %0;" : "+l"(acc) : "l"(a), "l"(b))
#define PACK2(dst, f)   asm("mov.b64 %0, {%1, %1};" : "=l"(dst) : "r"(__float_as_uint(f)))
#define UNPACK2(lo, hi, v) asm("mov.b64 {%0, %1}, %2;" : "=r"(lo), "=r"(hi) : "l"(v))

__global__ __launch_bounds__(576, 1)
void fused(const float* __restrict__ x, const float* __restrict__ w,
           const float* __restrict__ basis, const float* __restrict__ bias,
           const int* __restrict__ Tg, const int* __restrict__ Ig,
           const int* __restrict__ Jg, const int* __restrict__ bbg,
           float* __restrict__ out)
{
    const int vox = blockIdx.x;
    const int vx = vox / 144, vy = (vox / 12) % 12, vz = vox % 12;
    const int tid = threadIdx.x;

    // ---- boundary voxel: zero the 96 x 320 slice ----
    if (vx < 1 || vx > 9 || vy < 1 || vy > 9 || vz < 1 || vz > 9) {
        const float4 z4 = make_float4(0.f, 0.f, 0.f, 0.f);
        float* ob = out + (size_t)vox * 320;
        for (int i = tid; i < 7680; i += 576) {
            const int ch = i / 80, off = (i % 80) * 4;
            *reinterpret_cast<float4*>(ob + (size_t)ch * 552960 + off) = z4;
        }
        return;
    }

    extern __shared__ __align__(16) float sm[];
    float* Wsm    = sm;                 // 12096
    float* Ys     = sm + F_WSM;         // Ys[ob*356 + h*44 + w]
    float* accS   = Ys + F_YS;          // accS[((g*8+o)*6+p)*38 + q]
    float* Bs     = accS + F_ACCS;      // basis copy
    float* bias_s = Bs + F_BS;          // 8 sums
    int*   bb_s   = (int*)(bias_s + 8); // 96
    int*   pq_s   = bb_s + 96;          // 320 : (I-1)*38 + (J-1)

    // ---- cooperative preamble ----
    for (int idx = tid; idx < 12096; idx += 576) {
        int o = idx / 1512;  int r = idx - o * 1512;   // weight idx = o*1512 + c*189 + f*7 + b
        int c = r / 189;     r -= c * 189;
        int f = r / 7;       int b = r - f * 7;
        Wsm[(c * 27 + f) * 56 + o * 7 + b] = w[idx];
    }
    for (int i = tid; i < F_BS; i += 576) Bs[i] = basis[i];
    if (tid < 96) bb_s[tid] = bbg[tid];
    if (tid < 320) pq_s[tid] = (Ig[tid] - 1) * 38 + (Jg[tid] - 1);
    if (tid < 8) {
        float s = 0.f;
        for (int k = 0; k < 27; k++) s += bias[tid * 27 + k];
        bias_s[tid] = s;
    }
    __syncthreads();

    const int xo = vx - 1, yo = vy - 1, zo = vz - 1;

    // ---- part 1: Y = weight (*) x  (560 threads: 7 og-groups x 80 hw-quads,
    //      each thread 8 outputs x 4 w, FFMA2) ----
    if (tid < 560) {
        const int og  = tid / 80;            // 0..6 -> outputs [og*8, og*8+8)
        const int hwb = (tid % 80) * 4;
        // x strides (floats): c:552960  xi:46080  yi:3840  zi:320
        const float* xb = x + xo * 46080 + yo * 3840 + zo * 320 + hwb;

        unsigned long long a64[4][4];        // [out pair j][x elem k]
#pragma unroll
        for (int j = 0; j < 4; j++)
#pragma unroll
            for (int k = 0; k < 4; k++) a64[j][k] = 0ull;

        for (int c = 0; c < 8; c++) {
            const float* xc = xb + c * 552960;
            for (int fi = 0; fi < 3; fi++) {
                const float* xcf = xc + fi * 46080;
                const float* wcf = Wsm + (c * 27 + fi * 9) * 56 + og * 8;
#pragma unroll
                for (int f9 = 0; f9 < 9; f9++) {
                    const int fj = f9 / 3, fk = f9 % 3;
                    const float4 xv = *reinterpret_cast<const float4*>(
                        xcf + fj * 3840 + fk * 320);
                    unsigned long long xq0, xq1, xq2, xq3;
                    PACK2(xq0, xv.x); PACK2(xq1, xv.y);
                    PACK2(xq2, xv.z); PACK2(xq3, xv.w);
                    // 16B-aligned: f9*56 floats = 224B, og*8 floats = 32B
                    const ulonglong2 wAB =
                        *reinterpret_cast<const ulonglong2*>(wcf + f9 * 56);      // pairs 0,1
                    const ulonglong2 wCD =
                        *reinterpret_cast<const ulonglong2*>(wcf + f9 * 56 + 4);  // pairs 2,3
                    FMA2(a64[0][0], wAB.x, xq0); FMA2(a64[0][1], wAB.x, xq1);
                    FMA2(a64[0][2], wAB.x, xq2); FMA2(a64[0][3], wAB.x, xq3);
                    FMA2(a64[1][0], wAB.y, xq0); FMA2(a64[1][1], wAB.y, xq1);
                    FMA2(a64[1][2], wAB.y, xq2); FMA2(a64[1][3], wAB.y, xq3);
                    FMA2(a64[2][0], wCD.x, xq0); FMA2(a64[2][1], wCD.x, xq1);
                    FMA2(a64[2][2], wCD.x, xq2); FMA2(a64[2][3], wCD.x, xq3);
                    FMA2(a64[3][0], wCD.y, xq0); FMA2(a64[3][1], wCD.y, xq1);
                    FMA2(a64[3][2], wCD.y, xq2); FMA2(a64[3][3], wCD.y, xq3);
                }
            }
        }

        const int h = hwb / 40, w0 = hwb % 40;
#pragma unroll
        for (int j = 0; j < 4; j++) {
            float r0[4], r1[4];
#pragma unroll
            for (int k = 0; k < 4; k++) {
                unsigned lo, hi;
                UNPACK2(lo, hi, a64[j][k]);
                r0[k] = __uint_as_float(lo);
                r1[k] = __uint_as_float(hi);
            }
            float* p0 = Ys + (og * 8 + 2 * j) * YOBS + h * YROW + w0;
            *reinterpret_cast<float4*>(p0)        = make_float4(r0[0], r0[1], r0[2], r0[3]);
            *reinterpret_cast<float4*>(p0 + YOBS) = make_float4(r1[0], r1[1], r1[2], r1[3]);
        }
    }
    __syncthreads();

    // ---- part 2: basis conv, thread = (g,o,p), tid == (g*8+o)*6+p (scalar FFMA) ----
    {
        const int g = tid / 48;
        const int o = (tid / 6) % 8;
        const int p = tid % 6;
        float acc[38];
#pragma unroll
        for (int q = 0; q < 38; q++) acc[q] = 0.f;

        for (int b = 0; b < 7; b++) {
#pragma unroll
            for (int u = 0; u < 3; u++) {
                const float* yrow = Ys + (o * 7 + b) * YOBS + (p + u) * YROW;
                float r[40];
#pragma unroll
                for (int i = 0; i < 10; i++) {
                    const float4 v = reinterpret_cast<const float4*>(yrow)[i];
                    r[4*i] = v.x; r[4*i+1] = v.y; r[4*i+2] = v.z; r[4*i+3] = v.w;
                }
                const float* bp = Bs + ((g * 7 + b) * 3 + u) * 3;
                const float s0 = bp[0], s1 = bp[1], s2 = bp[2];
#pragma unroll
                for (int q = 0; q < 38; q++)
                    acc[q] += s0 * r[q] + s1 * r[q + 1] + s2 * r[q + 2];
            }
        }
        float* ad = accS + tid * 38;
#pragma unroll
        for (int q = 0; q < 38; q++) ad[q] = acc[q];
    }
    __syncthreads();

    // ---- gather + write interior slice ----
    float* ob = out + (size_t)vox * 320;
    for (int idx = tid; idx < 30720; idx += 576) {
        const int go = idx / 320;
        const int hw = idx - go * 320;
        const int g  = go >> 3, o = go & 7;
        const int t  = Tg[g * 320 + hw];
        const float v = accS[(t * 8 + o) * 228 + pq_s[hw]] + bias_s[bb_s[t * 8 + o]];
        ob[(size_t)go * 552960 + hw] = v;
    }
}

// ---------------------------------------------------------------------------
extern "C" void kernel_launch(void* const* d_in, const int* in_sizes, int n_in,
                              void* d_out, int out_size)
{
    const float* x      = (const float*)d_in[0];
    const float* weight = (const float*)d_in[1];
    const float* bias   = (const float*)d_in[2];
    const float* basis  = (const float*)d_in[3];
    const int*   Ig     = (const int*)d_in[4];
    const int*   Jg     = (const int*)d_in[5];
    const int*   Tg     = (const int*)d_in[6];
    const int*   bbg    = (const int*)d_in[7];
    float*       out    = (float*)d_out;

    const size_t smem = (size_t)(F_WSM + F_YS + F_ACCS + F_BS + 8) * sizeof(float)
                      + (96 + 320) * sizeof(int);               // 220,400 B
    cudaFuncSetAttribute(fused, cudaFuncAttributeMaxDynamicSharedMemorySize, (int)smem);
    fused<<<1728, 576, smem>>>(x, weight, basis, bias, Tg, Ig, Jg, bbg, out);
}